// round 12
// baseline (speedup 1.0000x reference)
#include <cuda_runtime.h>
#include <cuda_fp16.h>

#define Cc 10
#define Bb 512
#define Nn 1152
#define Ii 8
#define Oo 16

#define CHUNKS 8
#define BCH (Bb / CHUNKS)              // 64 b per chunk
#define PJ 16                          // batches per producer CTA
#define PSPLIT (BCH / PJ)              // 4
#define P_PER_CHUNK (9 * PSPLIT * Cc)  // 360
#define C_PER_CHUNK (Cc * BCH)         // 640
#define FLAG_TARGET (9 * PSPLIT)       // 36 producer CTAs feed one (c,chunk)
#define TOTAL_CTAS (CHUNKS * (P_PER_CHUNK + C_PER_CHUNK))  // 8000

// Scratch u_hat[C,B,N,O] in fp16 as uint4 (8 halves each) = 189 MB.
// With chunked produce->consume + discard, it lives in L2, not DRAM.
__device__ uint4 g_uhat[(size_t)Cc * Bb * Nn * Oo / 8];
__device__ unsigned g_flag[CHUNKS * Cc];  // 80 completion counters

typedef unsigned long long u64;

// ---- packed f32x2 helpers (ptxas never auto-fuses these from C++) ----
__device__ __forceinline__ u64 fma2(u64 a, u64 b, u64 c) {
    u64 d; asm("fma.rn.f32x2 %0, %1, %2, %3;" : "=l"(d) : "l"(a), "l"(b), "l"(c)); return d;
}
__device__ __forceinline__ u64 mul2(u64 a, u64 b) {
    u64 d; asm("mul.rn.f32x2 %0, %1, %2;" : "=l"(d) : "l"(a), "l"(b)); return d;
}
__device__ __forceinline__ u64 add2(u64 a, u64 b) {
    u64 d; asm("add.rn.f32x2 %0, %1, %2;" : "=l"(d) : "l"(a), "l"(b)); return d;
}
__device__ __forceinline__ u64 dup2(float x) {
    u64 d; asm("mov.b64 %0, {%1, %1};" : "=l"(d) : "f"(x)); return d;
}
__device__ __forceinline__ u64 pack2(float lo, float hi) {
    u64 d; asm("mov.b64 %0, {%1, %2};" : "=l"(d) : "f"(lo), "f"(hi)); return d;
}
__device__ __forceinline__ void unpack2(u64 a, float& lo, float& hi) {
    asm("mov.b64 {%0, %1}, %2;" : "=f"(lo), "=f"(hi) : "l"(a));
}
__device__ __forceinline__ unsigned cvth2(float lo, float hi) {
    __half2 h = __floats2half2_rn(lo, hi);
    return *(unsigned*)&h;
}
__device__ __forceinline__ u64 h2f2(unsigned w) {
    __half2 h = *(__half2*)&w;
    float2 f = __half22float2(h);
    return pack2(f.x, f.y);
}

// ---------------------------------------------------------------------------
__global__ void zero_flags() {
    int t = threadIdx.x;
    if (t < CHUNKS * Cc) g_flag[t] = 0;
}

// ---------------------------------------------------------------------------
// Fused kernel, SKEWED pipeline order:
//   [P0, P1, C0, P2, C1, P3, C2, ..., C5, P7, C6, C7]
// Consumers of chunk k are issued one full chunk after its producers, so by
// the time C_k gets SM slots, P_k has drained (near-zero spin), while P_{k+2}
// producers co-reside with C_k consumers and fill each other's stall slots.
// Every C_k still follows every P_k in bid order => deadlock-free under
// in-order CTA scheduling (same protocol R10 ran correctly).
// ---------------------------------------------------------------------------
__global__ __launch_bounds__(256) void fused_kernel(const float* __restrict__ u,
                                                    const float* __restrict__ W,
                                                    float* __restrict__ out) {
    const int bid = blockIdx.x;
    const int tid = threadIdx.x;

    int is_producer, chunk, idx;
    if (bid < 2 * P_PER_CHUNK) {  // P0, P1
        is_producer = 1; chunk = bid / P_PER_CHUNK; idx = bid % P_PER_CHUNK;
    } else if (bid < 2 * P_PER_CHUNK + 6 * (C_PER_CHUNK + P_PER_CHUNK)) {
        int t = bid - 2 * P_PER_CHUNK;
        int blk = t / (C_PER_CHUNK + P_PER_CHUNK);
        int r   = t % (C_PER_CHUNK + P_PER_CHUNK);
        if (r < C_PER_CHUNK) { is_producer = 0; chunk = blk;     idx = r; }
        else                 { is_producer = 1; chunk = blk + 2; idx = r - C_PER_CHUNK; }
    } else {                      // C6, C7
        int t = bid - (2 * P_PER_CHUNK + 6 * (C_PER_CHUNK + P_PER_CHUNK));
        is_producer = 0; chunk = 6 + t / C_PER_CHUNK; idx = t % C_PER_CHUNK;
    }

    if (is_producer) {
        // ================= producer =================
        const int c  = idx / (9 * PSPLIT);
        const int rr = idx % (9 * PSPLIT);
        const int nb = rr / PSPLIT;
        const int js = rr % PSPLIT;
        const int n  = nb * 128 + (tid >> 1);
        const int h  = tid & 1;
        const int b0 = chunk * BCH + js * PJ;

        // W[c,n,i, 8h..8h+7] as packed f32 pairs (64 regs)
        u64 w2[8][4];
        const float* wc = W + (((size_t)c * Nn + n) * Ii) * Oo + h * 8;
#pragma unroll
        for (int i = 0; i < 8; i++) {
            ulonglong2 aa = *(const ulonglong2*)(wc + i * Oo);
            ulonglong2 bb = *(const ulonglong2*)(wc + i * Oo + 4);
            w2[i][0] = aa.x; w2[i][1] = aa.y; w2[i][2] = bb.x; w2[i][3] = bb.y;
        }

        const float* ub = u + ((size_t)b0 * Nn + n) * Ii;
        uint4* ob = g_uhat + (((size_t)c * Bb + b0) * Nn + n) * 2 + h;

#pragma unroll 4
        for (int j = 0; j < PJ; j++) {
            const float4* up = (const float4*)(ub + (size_t)j * (Nn * Ii));
            float4 a = __ldg(up);
            float4 b = __ldg(up + 1);
            float usv[8] = {a.x, a.y, a.z, a.w, b.x, b.y, b.z, b.w};

            u64 acc[4];
            {
                u64 ud = dup2(usv[0]);
#pragma unroll
                for (int k = 0; k < 4; k++) acc[k] = mul2(ud, w2[0][k]);
            }
#pragma unroll
            for (int i = 1; i < 8; i++) {
                u64 ud = dup2(usv[i]);
#pragma unroll
                for (int k = 0; k < 4; k++) acc[k] = fma2(ud, w2[i][k], acc[k]);
            }
            float r2[8];
#pragma unroll
            for (int k = 0; k < 4; k++) unpack2(acc[k], r2[2 * k], r2[2 * k + 1]);

            uint4 st;
            st.x = cvth2(r2[0], r2[1]);
            st.y = cvth2(r2[2], r2[3]);
            st.z = cvth2(r2[4], r2[5]);
            st.w = cvth2(r2[6], r2[7]);
            ob[(size_t)j * (Nn * 2)] = st;  // default store: keep in L2
        }

        // completion: make stores visible, then release-add the flag
        __threadfence();
        __syncthreads();
        if (tid == 0) {
            unsigned* f = &g_flag[chunk * Cc + c];
            asm volatile("red.release.gpu.global.add.u32 [%0], %1;"
                         :: "l"(f), "r"(1u) : "memory");
        }
        return;
    }

    // ================= consumer (R6 routing) =================
    const int c    = idx / BCH;
    const int b    = chunk * BCH + (idx % BCH);
    const int lane = tid & 31, wid = tid >> 5;
    const int nl   = tid >> 1, h = tid & 1;

    __shared__ float red[8][2][12];  // [warp][half][S0..7, z]
    __shared__ float Vs[16];         // accumulated v

    // wait for this (c,chunk)'s 36 producer CTAs
    if (tid == 0) {
        const unsigned* f = &g_flag[chunk * Cc + c];
        unsigned v;
        while (true) {
            asm volatile("ld.acquire.gpu.global.u32 %0, [%1];" : "=r"(v) : "l"(f));
            if (v >= FLAG_TARGET) break;
            __nanosleep(200);
        }
    }
    __syncthreads();

    // Load slab (L2 hits): one uint4 (8 fp16) per row; convert once to f32x2.
    u64 uh[9][4];
    const uint4* p = g_uhat + ((size_t)c * Bb + b) * (size_t)(Nn * 2);
#pragma unroll
    for (int r = 0; r < 9; r++) {
        uint4 t = p[(size_t)(r * 128 + nl) * 2 + h];
        uh[r][0] = h2f2(t.x);
        uh[r][1] = h2f2(t.y);
        uh[r][2] = h2f2(t.z);
        uh[r][3] = h2f2(t.w);
    }

    // All loads consumed -> barrier -> drop dirty lines from L2
    // (slab is private to this CTA; 36864 B = 288 lines of 128 B).
    __syncthreads();
    {
        const char* sb = (const char*)p;
        for (int L = tid; L < 288; L += 256)
            asm volatile("discard.global.L2 [%0], 128;" :: "l"(sb + (size_t)L * 128) : "memory");
    }

    for (int it = 0; it < 3; it++) {
        float S[8], z;
        u64 S2[4] = {0ull, 0ull, 0ull, 0ull};
        if (it == 0) {
#pragma unroll
            for (int r = 0; r < 9; r++)
#pragma unroll
                for (int k = 0; k < 4; k++) S2[k] = add2(S2[k], uh[r][k]);
            z = 9.0f;  // 9 rows, unit weight
        } else {
            u64 V2[4];
#pragma unroll
            for (int k = 0; k < 4; k++)
                V2[k] = pack2(Vs[8 * h + 2 * k], Vs[8 * h + 2 * k + 1]);
            z = 0.0f;
#pragma unroll
            for (int r = 0; r < 9; r++) {
                u64 d = mul2(uh[r][0], V2[0]);
                d = fma2(uh[r][1], V2[1], d);
                d = fma2(uh[r][2], V2[2], d);
                d = fma2(uh[r][3], V2[3], d);
                float lo, hi; unpack2(d, lo, hi);
                float a = lo + hi;
                a += __shfl_xor_sync(0xffffffffu, a, 1);  // partner o-half
                float e = __expf(a);
                z += e;
                u64 ed = dup2(e);
#pragma unroll
                for (int k = 0; k < 4; k++) S2[k] = fma2(ed, uh[r][k], S2[k]);
            }
        }
#pragma unroll
        for (int k = 0; k < 4; k++) unpack2(S2[k], S[2 * k], S[2 * k + 1]);

        // Reduce over the 16 same-half lanes of each warp (xor 2,4,8,16)
#pragma unroll
        for (int off = 2; off <= 16; off <<= 1) {
            z += __shfl_xor_sync(0xffffffffu, z, off);
#pragma unroll
            for (int o = 0; o < 8; o++)
                S[o] += __shfl_xor_sync(0xffffffffu, S[o], off);
        }
        if (lane < 2) {  // lane 0 = half 0, lane 1 = half 1
#pragma unroll
            for (int o = 0; o < 8; o++) red[wid][lane][o] = S[o];
            red[wid][lane][8] = z;
        }
        __syncthreads();

        // Final combine + squash: 16 threads, one per o
        if (tid < 16) {
            int o = tid, hh = o >> 3, k = o & 7;
            float s = 0.0f, Z = 0.0f;
#pragma unroll
            for (int w = 0; w < 8; w++) { s += red[w][hh][k]; Z += red[w][0][8]; }
            s /= Z;
            float sn = s * s;
#pragma unroll
            for (int off = 1; off <= 8; off <<= 1)
                sn += __shfl_xor_sync(0xffffu, sn, off);
            float fq = (sn / (1.0f + sn)) * rsqrtf(sn);
            float v = s * fq;
            if (it == 2) out[((size_t)c * Bb + b) * Oo + o] = v;
            else Vs[o] = (it == 0) ? v : (Vs[o] + v);
        }
        __syncthreads();
    }
}

// ---------------------------------------------------------------------------
extern "C" void kernel_launch(void* const* d_in, const int* in_sizes, int n_in,
                              void* d_out, int out_size) {
    const float* u = (const float*)d_in[0];  // [B,N,I]
    const float* W = (const float*)d_in[1];  // [C,N,I,O]
    float* out = (float*)d_out;              // [C,B,1,1,O]

    zero_flags<<<1, 128>>>();
    fused_kernel<<<TOTAL_CTAS, 256>>>(u, W, out);
}

// round 14
// speedup vs baseline: 1.2384x; 1.2384x over previous
#include <cuda_runtime.h>
#include <cuda_fp16.h>

#define Cc 10
#define Bb 512
#define Nn 1152
#define Ii 8
#define Oo 16

// Scratch u_hat[C,B,N,O] in fp16, stored as uint4 (8 halves per uint4) = 189 MB
__device__ uint4 g_uhat[(size_t)Cc * Bb * Nn * Oo / 8];

typedef unsigned long long u64;

// ---- packed f32x2 helpers (ptxas never auto-fuses these from C++) ----
__device__ __forceinline__ u64 fma2(u64 a, u64 b, u64 c) {
    u64 d; asm("fma.rn.f32x2 %0, %1, %2, %3;" : "=l"(d) : "l"(a), "l"(b), "l"(c)); return d;
}
__device__ __forceinline__ u64 mul2(u64 a, u64 b) {
    u64 d; asm("mul.rn.f32x2 %0, %1, %2;" : "=l"(d) : "l"(a), "l"(b)); return d;
}
__device__ __forceinline__ u64 add2(u64 a, u64 b) {
    u64 d; asm("add.rn.f32x2 %0, %1, %2;" : "=l"(d) : "l"(a), "l"(b)); return d;
}
__device__ __forceinline__ u64 dup2(float x) {
    u64 d; asm("mov.b64 %0, {%1, %1};" : "=l"(d) : "f"(x)); return d;
}
__device__ __forceinline__ u64 pack2(float lo, float hi) {
    u64 d; asm("mov.b64 %0, {%1, %2};" : "=l"(d) : "f"(lo), "f"(hi)); return d;
}
__device__ __forceinline__ void unpack2(u64 a, float& lo, float& hi) {
    asm("mov.b64 {%0, %1}, %2;" : "=f"(lo), "=f"(hi) : "l"(a));
}
__device__ __forceinline__ unsigned cvth2(float lo, float hi) {
    __half2 h = __floats2half2_rn(lo, hi);
    return *(unsigned*)&h;
}
__device__ __forceinline__ u64 h2f2(unsigned w) {
    __half2 h = *(__half2*)&w;
    float2 f = __half22float2(h);
    return pack2(f.x, f.y);
}

// ---------------------------------------------------------------------------
// Phase 1 (R6 verbatim -- measured ~53 us):
// u_hat[c,b,n,o] = sum_i u[b,n,i] * W[c,n,i,o], stored fp16.
// 256 thr = 128 n x 2 o-halves, W in 64 regs, 64-batch loop.
// Grid: (9, 8, 10) = 720 CTAs.
// ---------------------------------------------------------------------------
__global__ __launch_bounds__(256) void uhat_kernel(const float* __restrict__ u,
                                                   const float* __restrict__ W) {
    const int tid = threadIdx.x;
    const int n   = blockIdx.x * 128 + (tid >> 1);
    const int h   = tid & 1;
    const int b0  = blockIdx.y * 64;
    const int c   = blockIdx.z;

    u64 w2[8][4];
    const float* wc = W + (((size_t)c * Nn + n) * Ii) * Oo + h * 8;
#pragma unroll
    for (int i = 0; i < 8; i++) {
        ulonglong2 aa = *(const ulonglong2*)(wc + i * Oo);
        ulonglong2 bb = *(const ulonglong2*)(wc + i * Oo + 4);
        w2[i][0] = aa.x; w2[i][1] = aa.y; w2[i][2] = bb.x; w2[i][3] = bb.y;
    }

    const float* ub = u + ((size_t)b0 * Nn + n) * Ii;
    uint4* ob = g_uhat + (((size_t)c * Bb + b0) * Nn + n) * 2 + h;

#pragma unroll 4
    for (int j = 0; j < 64; j++) {
        const float4* up = (const float4*)(ub + (size_t)j * (Nn * Ii));
        float4 a = __ldg(up);
        float4 b = __ldg(up + 1);
        float usv[8] = {a.x, a.y, a.z, a.w, b.x, b.y, b.z, b.w};

        u64 acc[4];
        {
            u64 ud = dup2(usv[0]);
#pragma unroll
            for (int k = 0; k < 4; k++) acc[k] = mul2(ud, w2[0][k]);
        }
#pragma unroll
        for (int i = 1; i < 8; i++) {
            u64 ud = dup2(usv[i]);
#pragma unroll
            for (int k = 0; k < 4; k++) acc[k] = fma2(ud, w2[i][k], acc[k]);
        }
        float r[8];
#pragma unroll
        for (int k = 0; k < 4; k++) unpack2(acc[k], r[2 * k], r[2 * k + 1]);

        uint4 st;
        st.x = cvth2(r[0], r[1]);
        st.y = cvth2(r[2], r[3]);
        st.z = cvth2(r[4], r[5]);
        st.w = cvth2(r[6], r[7]);
        __stcs(ob + (size_t)j * (Nn * 2), st);
    }
}

// ---------------------------------------------------------------------------
// Phase 2: routing, R6 structure with the S-reduction replaced by a
// SPLIT-BUTTERFLY: 8 values over 16 same-half lanes reduce with 8 shfls
// (4+2+1 halving rounds + 1 full fold) instead of 32 shfl + 32 add.
// Lane L ends owning the total for o = 8*(L&1) + 4*b1 + 2*b2 + b3, so lanes
// 0..15 cover all 16 o's uniquely -> direct smem write, same combiner as R6.
// Grid: (B, C), reverse walk; 256 thr/CTA, slab in 72 f32 regs.
// ---------------------------------------------------------------------------
__global__ __launch_bounds__(256, 2) void routing_kernel(float* __restrict__ out) {
    const int tid  = threadIdx.x;
    const int b    = (Bb - 1) - blockIdx.x;
    const int c    = (Cc - 1) - blockIdx.y;
    const int lane = tid & 31, wid = tid >> 5;
    const int nl   = tid >> 1, h = tid & 1;

    __shared__ float red[8][17];  // [warp][o0..15, z]
    __shared__ float Vs[16];      // accumulated v

    // Load slab: one uint4 (8 fp16) per row per thread; convert once to f32x2.
    u64 uh[9][4];
    const uint4* p = g_uhat + ((size_t)c * Bb + b) * (size_t)(Nn * 2);
#pragma unroll
    for (int r = 0; r < 9; r++) {
        uint4 t = __ldcs(p + (size_t)(r * 128 + nl) * 2 + h);
        uh[r][0] = h2f2(t.x);
        uh[r][1] = h2f2(t.y);
        uh[r][2] = h2f2(t.z);
        uh[r][3] = h2f2(t.w);
    }

    const bool up1 = (lane >> 1) & 1;
    const bool up2 = (lane >> 2) & 1;
    const bool up3 = (lane >> 3) & 1;
    const int  o_of_lane = 8 * (lane & 1) + 4 * ((lane >> 1) & 1) +
                           2 * ((lane >> 2) & 1) + ((lane >> 3) & 1);

    for (int it = 0; it < 3; it++) {
        float S[8], z = 0.0f;
        u64 S2[4] = {0ull, 0ull, 0ull, 0ull};
        if (it == 0) {
#pragma unroll
            for (int r = 0; r < 9; r++)
#pragma unroll
                for (int k = 0; k < 4; k++) S2[k] = add2(S2[k], uh[r][k]);
        } else {
            u64 V2[4];
#pragma unroll
            for (int k = 0; k < 4; k++)
                V2[k] = pack2(Vs[8 * h + 2 * k], Vs[8 * h + 2 * k + 1]);
#pragma unroll
            for (int r = 0; r < 9; r++) {
                u64 d = mul2(uh[r][0], V2[0]);
                d = fma2(uh[r][1], V2[1], d);
                d = fma2(uh[r][2], V2[2], d);
                d = fma2(uh[r][3], V2[3], d);
                float lo, hi; unpack2(d, lo, hi);
                float a = lo + hi;
                a += __shfl_xor_sync(0xffffffffu, a, 1);  // partner o-half
                float e = __expf(a);
                z += e;
                u64 ed = dup2(e);
#pragma unroll
                for (int k = 0; k < 4; k++) S2[k] = fma2(ed, uh[r][k], S2[k]);
            }
        }
#pragma unroll
        for (int k = 0; k < 4; k++) unpack2(S2[k], S[2 * k], S[2 * k + 1]);

        // --- split-butterfly S-reduce over the 16 same-half lanes ---
        float v4[4];
#pragma unroll
        for (int k = 0; k < 4; k++) {
            float send = up1 ? S[k] : S[k + 4];
            float recv = __shfl_xor_sync(0xffffffffu, send, 2);
            v4[k] = (up1 ? S[k + 4] : S[k]) + recv;
        }
        float v2[2];
#pragma unroll
        for (int k = 0; k < 2; k++) {
            float send = up2 ? v4[k] : v4[k + 2];
            float recv = __shfl_xor_sync(0xffffffffu, send, 4);
            v2[k] = (up2 ? v4[k + 2] : v4[k]) + recv;
        }
        float v1;
        {
            float send = up3 ? v2[0] : v2[1];
            float recv = __shfl_xor_sync(0xffffffffu, send, 8);
            v1 = (up3 ? v2[1] : v2[0]) + recv;
        }
        v1 += __shfl_xor_sync(0xffffffffu, v1, 16);
        // v1 = S_total[o_of_lane], lanes 0..15 cover all o uniquely

        // z tree over the 16 same-parity lanes (it>0 only)
        if (it > 0) {
#pragma unroll
            for (int off = 2; off <= 16; off <<= 1)
                z += __shfl_xor_sync(0xffffffffu, z, off);
        }

        if (lane < 16) red[wid][o_of_lane] = v1;
        if (lane == 0) red[wid][16] = z;
        __syncthreads();

        // Final combine + squash: 16 threads, one per o
        if (tid < 16) {
            int o = tid;
            float s = 0.0f, Z = 0.0f;
#pragma unroll
            for (int w = 0; w < 8; w++) { s += red[w][o]; Z += red[w][16]; }
            if (it == 0) Z = (float)Nn;  // softmax of zeros: Z exactly N
            s /= Z;
            float sn = s * s;
#pragma unroll
            for (int off = 1; off <= 8; off <<= 1)
                sn += __shfl_xor_sync(0xffffu, sn, off);
            float fq = (sn / (1.0f + sn)) * rsqrtf(sn);
            float v = s * fq;
            if (it == 2) out[((size_t)c * Bb + b) * Oo + o] = v;
            else Vs[o] = (it == 0) ? v : (Vs[o] + v);
        }
        __syncthreads();
    }
}

// ---------------------------------------------------------------------------
extern "C" void kernel_launch(void* const* d_in, const int* in_sizes, int n_in,
                              void* d_out, int out_size) {
    const float* u = (const float*)d_in[0];  // [B,N,I]
    const float* W = (const float*)d_in[1];  // [C,N,I,O]
    float* out = (float*)d_out;              // [C,B,1,1,O]

    uhat_kernel<<<dim3(Nn / 128, Bb / 64, Cc), 256>>>(u, W);
    routing_kernel<<<dim3(Bb, Cc), 256>>>(out);
}